// round 8
// baseline (speedup 1.0000x reference)
#include <cuda_runtime.h>
#include <cstdint>

// ---------------- problem constants ----------------
#define NTOT   8192
#define BHALF  4096
#define DD     256
#define TILE   128
#define KCB    128      // K-chunk BYTES per row (swizzle atom) = 128 int8
#define NCHUNK 2        // 256 / 128
#define NT     256      // 8 warps, 2x4 warp grid
#define NTILES 64
#define NBLK   (NTILES * (NTILES + 1) / 2)   // 2080

#define QSCALE (127.0f / 5.5f)   // int8 quantization scale

// smem: [A0 16K][B0 16K][A1 16K][B1 16K][sq 1K][red 32B]
#define STAGE_BYTES 32768u
#define B_OFF       16384u
#define SQ_OFF      65536u
#define RED_OFF     66560u
#define SMEM_TOTAL  66624

// ---------------- device scratch ----------------
__device__ int8_t   g_xq[NTOT * DD];   // quantized inputs
__device__ int      g_sqi[NTOT];       // integer row squared norms
__device__ int      g_sqpart[1024];
__device__ int      g_colpart[32 * DD];
__device__ float    g_ms;              // log2(e)/(16*bw) in q^2 units
__device__ double   g_acc;
__device__ unsigned g_cnt1;            // zero-init; self-resetting
__device__ unsigned g_cnt2;

// ---------------- helpers ----------------
__device__ __forceinline__ uint32_t smem_u32(const void* p) {
    uint32_t a;
    asm("{ .reg .u64 t; cvta.to.shared.u64 t, %1; cvt.u32.u64 %0, t; }"
        : "=r"(a) : "l"(p));
    return a;
}
__device__ __forceinline__ void ldsm_x4(uint32_t& r0, uint32_t& r1,
                                        uint32_t& r2, uint32_t& r3,
                                        uint32_t addr) {
    asm volatile("ldmatrix.sync.aligned.m8n8.x4.shared.b16 {%0,%1,%2,%3}, [%4];"
                 : "=r"(r0), "=r"(r1), "=r"(r2), "=r"(r3) : "r"(addr));
}
// s8 MMA, exact s32 accumulation
__device__ __forceinline__ void mma_s8(int* d, const uint32_t* a,
                                       uint32_t b0, uint32_t b1) {
    asm volatile(
        "mma.sync.aligned.m16n8k32.row.col.s32.s8.s8.s32 "
        "{%0,%1,%2,%3}, {%4,%5,%6,%7}, {%8,%9}, {%0,%1,%2,%3};"
        : "+r"(d[0]), "+r"(d[1]), "+r"(d[2]), "+r"(d[3])
        : "r"(a[0]), "r"(a[1]), "r"(a[2]), "r"(a[3]), "r"(b0), "r"(b1));
}

// ---------------- prep: quantize to int8, integer row norms ----------------
__global__ void convert_kernel(const float* __restrict__ xs,
                               const float* __restrict__ xt) {
    int wid = threadIdx.x >> 5, lane = threadIdx.x & 31;
    int row = blockIdx.x * 8 + wid;
    const float* p = (row < BHALF) ? xs + (size_t)row * DD
                                   : xt + (size_t)(row - BHALF) * DD;

    int c0 = lane * 8;
    float4 v0 = *(const float4*)(p + c0);
    float4 v1 = *(const float4*)(p + c0 + 4);
    float f[8] = {v0.x, v0.y, v0.z, v0.w, v1.x, v1.y, v1.z, v1.w};
    int q[8], s = 0;
    #pragma unroll
    for (int j = 0; j < 8; j++) {
        float scaled = fminf(fmaxf(f[j] * QSCALE, -127.f), 127.f);
        q[j] = __float2int_rn(scaled);
        s += q[j] * q[j];
    }
    // pack 8 int8 -> int2
    int2 pk;
    pk.x = (q[0] & 0xFF) | ((q[1] & 0xFF) << 8) | ((q[2] & 0xFF) << 16) | (q[3] << 24);
    pk.y = (q[4] & 0xFF) | ((q[5] & 0xFF) << 8) | ((q[6] & 0xFF) << 16) | (q[7] << 24);
    *(int2*)(g_xq + (size_t)row * DD + c0) = pk;

    #pragma unroll
    for (int o = 16; o; o >>= 1) s += __shfl_xor_sync(0xffffffffu, s, o);
    __shared__ int ws[8];
    if (lane == 0) { ws[wid] = s; g_sqi[row] = s; }
    __syncthreads();
    if (threadIdx.x == 0) {
        int b = 0;
        #pragma unroll
        for (int w = 0; w < 8; w++) b += ws[w];
        g_sqpart[blockIdx.x] = b;
    }
}

// ---------------- colsum (32 blocks) + fused bandwidth in last block ----------------
__global__ void colsum_bw_kernel() {
    int t = threadIdx.x;
    int r0 = blockIdx.x * 256;
    int s = 0;
    for (int r = r0; r < r0 + 256; r++)
        s += (int)g_xq[(size_t)r * DD + t];
    g_colpart[blockIdx.x * DD + t] = s;

    __shared__ int s_last;
    __threadfence();
    __syncthreads();
    if (t == 0) s_last = (atomicAdd(&g_cnt1, 1u) == 31u);
    __syncthreads();
    if (!s_last) return;

    __shared__ double sh[256];
    int cs = 0;
    #pragma unroll 4
    for (int b = 0; b < 32; b++) cs += g_colpart[b * DD + t];
    double sq = 0.0;
    #pragma unroll
    for (int i = 0; i < 4; i++) sq += (double)g_sqpart[t + 256 * i];

    sh[t] = (double)cs * (double)cs;
    __syncthreads();
    for (int s2 = 128; s2; s2 >>= 1) { if (t < s2) sh[t] += sh[t + s2]; __syncthreads(); }
    double cs_tot = sh[0];
    __syncthreads();
    sh[t] = sq;
    __syncthreads();
    for (int s2 = 128; s2; s2 >>= 1) { if (t < s2) sh[t] += sh[t + s2]; __syncthreads(); }
    if (t == 0) {
        double sumsq = sh[0];                       // sum of q^2 (exact)
        double n = (double)NTOT;
        double sumL2 = 2.0 * n * sumsq - 2.0 * cs_tot;   // q^2 units
        double bw = sumL2 / (n * n - n) / 4.0;           // q^2 units
        g_ms = (float)(1.4426950408889634 / (bw * 16.0));
        g_acc = 0.0;
        g_cnt1 = 0u;
    }
}

// ---------------- chunk loader: 2048 x 16B, 8 per thread ----------------
__device__ __forceinline__ void load_chunk(uint32_t sb, int buf,
                                           const int8_t* gA, const int8_t* gB,
                                           int k0, int tid) {
    uint32_t aB = sb + buf * STAGE_BYTES;
    uint32_t bB = aB + B_OFF;
    #pragma unroll
    for (int i = 0; i < 4; i++) {
        int u = tid + i * 256;
        int row = u >> 3, c = u & 7;
        uint32_t off = (uint32_t)(row * 128 + c * 16);
        uint32_t sw = off ^ ((off >> 3) & 0x70);
        const int8_t* srcA = gA + (size_t)row * DD + k0 + c * 16;
        const int8_t* srcB = gB + (size_t)row * DD + k0 + c * 16;
        asm volatile("cp.async.cg.shared.global [%0], [%1], 16;"
                     :: "r"(aB + sw), "l"(srcA));
        asm volatile("cp.async.cg.shared.global [%0], [%1], 16;"
                     :: "r"(bB + sw), "l"(srcB));
    }
    asm volatile("cp.async.commit_group;" ::: "memory");
}

// ---------------- main int8 tensor-core kernel ----------------
__global__ void __launch_bounds__(NT, 2) mmd_mma_kernel(float* __restrict__ out) {
    int b = blockIdx.x;
    int ti = (int)((sqrtf(8.f * (float)b + 1.f) - 1.f) * 0.5f);
    while ((ti + 1) * (ti + 2) / 2 <= b) ti++;
    while (ti * (ti + 1) / 2 > b) ti--;
    int tj = b - ti * (ti + 1) / 2;

    extern __shared__ char smem[];
    uint32_t sb = smem_u32(smem);
    int tid = threadIdx.x, wid = tid >> 5, lane = tid & 31;

    const int8_t* gA = g_xq + (size_t)ti * TILE * DD;
    const int8_t* gB = g_xq + (size_t)tj * TILE * DD;

    load_chunk(sb, 0, gA, gB, 0, tid);

    // stage integer sq slices for the epilogue
    int* sqrow = (int*)(smem + SQ_OFF);              // 128
    int* sqcol = sqrow + TILE;                       // 128
    if (tid < TILE) sqrow[tid] = g_sqi[ti * TILE + tid];
    else            sqcol[tid - TILE] = g_sqi[tj * TILE + (tid - TILE)];

    int wm = (wid >> 2) * 64;
    int wn = (wid & 3) * 32;

    int acc[4][4][4];
    #pragma unroll
    for (int a = 0; a < 4; a++)
        #pragma unroll
        for (int c = 0; c < 4; c++)
            #pragma unroll
            for (int e = 0; e < 4; e++) acc[a][c][e] = 0;

    // s8 k32 fragments have the SAME byte layout as f16 k16 (b16 = 2 int8):
    // identical ldmatrix addressing, rows of 128 bytes.
    int grp = lane >> 3, rin = lane & 7;
    int aRow = wm + (grp & 1) * 8 + rin;
    int aKB  = (grp >> 1) * 16;
    int bRow = wn + (grp >> 1) * 8 + rin;
    int bKB  = (grp & 1) * 16;
    uint32_t aMask = (uint32_t)((aRow & 7) << 4);
    uint32_t bMask = (uint32_t)((bRow & 7) << 4);

    #pragma unroll
    for (int ck = 0; ck < NCHUNK; ck++) {
        if (ck < NCHUNK - 1) {
            load_chunk(sb, (ck + 1) & 1, gA, gB, (ck + 1) * KCB, tid);
            asm volatile("cp.async.wait_group 1;" ::: "memory");
        } else {
            asm volatile("cp.async.wait_group 0;" ::: "memory");
        }
        __syncthreads();

        uint32_t aB = sb + (uint32_t)(ck & 1) * STAGE_BYTES;
        uint32_t bB = aB + B_OFF;

        #pragma unroll
        for (int ks = 0; ks < 4; ks++) {     // four k32 steps per 128-byte chunk
            uint32_t a[4][4], bf[2][4];
            #pragma unroll
            for (int mt = 0; mt < 4; mt++) {
                uint32_t addr = aB + (uint32_t)((aRow + mt * 16) * 128)
                              + (((uint32_t)(ks * 32 + aKB)) ^ aMask);
                ldsm_x4(a[mt][0], a[mt][1], a[mt][2], a[mt][3], addr);
            }
            #pragma unroll
            for (int nh = 0; nh < 2; nh++) {
                uint32_t addr = bB + (uint32_t)((bRow + nh * 16) * 128)
                              + (((uint32_t)(ks * 32 + bKB)) ^ bMask);
                ldsm_x4(bf[nh][0], bf[nh][1], bf[nh][2], bf[nh][3], addr);
            }
            #pragma unroll
            for (int mt = 0; mt < 4; mt++)
                #pragma unroll
                for (int nt = 0; nt < 4; nt++)
                    mma_s8(acc[mt][nt], a[mt],
                           bf[nt >> 1][(nt & 1) * 2],
                           bf[nt >> 1][(nt & 1) * 2 + 1]);
        }
        __syncthreads();
    }

    // ---- epilogue: integer L2 -> 5-kernel RBF sum (one EX2 + 4 squarings) ----
    float ms = g_ms;
    int rbase = wm + (lane >> 2);
    int cbase = wn + ((lane & 3) << 1);
    int rglob = ti * TILE, cglob = tj * TILE;
    float total = 0.f;
    #pragma unroll
    for (int mt = 0; mt < 4; mt++) {
        int rr = rbase + mt * 16;
        #pragma unroll
        for (int nt = 0; nt < 4; nt++) {
            int cc = cbase + nt * 8;
            int sb0 = sqcol[cc], sb1 = sqcol[cc + 1];
            #pragma unroll
            for (int e = 0; e < 4; e++) {
                int rl = rr + ((e >> 1) << 3);
                int cl = cc + (e & 1);
                int sa = sqrow[rl];
                int sbv = (e & 1) ? sb1 : sb0;
                int diff = sa + sbv - 2 * acc[mt][nt][e];   // exact integer L2 (q^2)
                float fd = (float)max(diff, 0);
                float e0;
                asm("ex2.approx.ftz.f32 %0, %1;" : "=f"(e0) : "f"(-fd * ms));
                float e1 = e0 * e0, e2 = e1 * e1, e3 = e2 * e2, e4 = e3 * e3;
                float kv = ((e0 + e1) + (e2 + e3)) + e4;
                total += ((rglob + rl) > (cglob + cl)) ? kv : 0.f;
            }
        }
    }
    total *= (((ti < 32) == (tj < 32)) ? 2.f : -2.f);

    #pragma unroll
    for (int o = 16; o; o >>= 1) total += __shfl_xor_sync(0xffffffffu, total, o);
    float* red = (float*)(smem + RED_OFF);
    if (lane == 0) red[wid] = total;
    __syncthreads();
    if (tid == 0) {
        float s = 0.f;
        #pragma unroll
        for (int w = 0; w < 8; w++) s += red[w];
        atomicAdd(&g_acc, (double)s);
        __threadfence();
        if (atomicAdd(&g_cnt2, 1u) == (unsigned)NBLK - 1u) {
            out[0] = (float)((g_acc + (double)NTOT * 5.0) /
                             ((double)BHALF * (double)BHALF));
            g_cnt2 = 0u;
        }
    }
}

// ---------------- launch ----------------
extern "C" void kernel_launch(void* const* d_in, const int* in_sizes, int n_in,
                              void* d_out, int out_size) {
    const float* xs = (const float*)d_in[0];
    const float* xt = (const float*)d_in[1];
    float* out = (float*)d_out;

    cudaFuncSetAttribute(mmd_mma_kernel,
                         cudaFuncAttributeMaxDynamicSharedMemorySize, SMEM_TOTAL);

    convert_kernel<<<NTOT / 8, 256>>>(xs, xt);
    colsum_bw_kernel<<<32, 256>>>();
    mmd_mma_kernel<<<NBLK, NT, SMEM_TOTAL>>>(out);
}

// round 9
// speedup vs baseline: 1.7853x; 1.7853x over previous
#include <cuda_runtime.h>
#include <cuda_fp16.h>
#include <cstdint>

// ---------------- problem constants ----------------
#define NTOT   8192
#define BHALF  4096
#define DD     256
#define TILE   128
#define KC     64       // K-chunk halves = 128 B/row (swizzle atom)
#define NCHUNK 4        // 256 / 64
#define NT     256      // 8 warps, 2x4 warp grid
#define NTILES 64
#define NBLK   (NTILES * (NTILES + 1) / 2)   // 2080

// smem: [A0 16K][B0 16K][A1 16K][B1 16K][sq 1K][red 32B][ms 32B]
#define STAGE_BYTES 32768u
#define B_OFF       16384u
#define SQ_OFF      65536u
#define RED_OFF     66560u
#define MS_OFF      66592u
#define SMEM_TOTAL  66624

// ---------------- device scratch ----------------
__device__ __half   g_x[NTOT * DD];
__device__ float    g_sq[NTOT];
__device__ float    g_colsum[DD];     // zero-init; reset by last finisher
__device__ double   g_sumsq;          // zero-init; reset by last finisher
__device__ double   g_acc;
__device__ unsigned g_bar;            // zero-init; reset by last finisher
__device__ unsigned g_done;

// ---------------- helpers ----------------
__device__ __forceinline__ uint32_t smem_u32(const void* p) {
    uint32_t a;
    asm("{ .reg .u64 t; cvta.to.shared.u64 t, %1; cvt.u32.u64 %0, t; }"
        : "=r"(a) : "l"(p));
    return a;
}
__device__ __forceinline__ void ldsm_x4(uint32_t& r0, uint32_t& r1,
                                        uint32_t& r2, uint32_t& r3,
                                        uint32_t addr) {
    asm volatile("ldmatrix.sync.aligned.m8n8.x4.shared.b16 {%0,%1,%2,%3}, [%4];"
                 : "=r"(r0), "=r"(r1), "=r"(r2), "=r"(r3) : "r"(addr));
}
__device__ __forceinline__ void mma_f16acc(uint32_t* d, const uint32_t* a,
                                           uint32_t b0, uint32_t b1) {
    asm volatile(
        "mma.sync.aligned.m16n8k16.row.col.f16.f16.f16.f16 "
        "{%0,%1}, {%2,%3,%4,%5}, {%6,%7}, {%0,%1};"
        : "+r"(d[0]), "+r"(d[1])
        : "r"(a[0]), "r"(a[1]), "r"(a[2]), "r"(a[3]), "r"(b0), "r"(b1));
}
__device__ __forceinline__ void tile_decode(int b, int& ti, int& tj) {
    int t = (int)((sqrtf(8.f * (float)b + 1.f) - 1.f) * 0.5f);
    while ((t + 1) * (t + 2) / 2 <= b) t++;
    while (t * (t + 1) / 2 > b) t--;
    ti = t; tj = b - t * (t + 1) / 2;
}
__device__ __forceinline__ void load_chunk(uint32_t sb, int buf,
                                           const __half* gA, const __half* gB,
                                           int k0, int tid) {
    uint32_t aB = sb + buf * STAGE_BYTES;
    uint32_t bB = aB + B_OFF;
    #pragma unroll
    for (int i = 0; i < 4; i++) {
        int u = tid + i * 256;
        int row = u >> 3, c = u & 7;
        uint32_t off = (uint32_t)(row * 128 + c * 16);
        uint32_t sw = off ^ ((off >> 3) & 0x70);
        const __half* srcA = gA + (size_t)row * DD + k0 + c * 8;
        const __half* srcB = gB + (size_t)row * DD + k0 + c * 8;
        asm volatile("cp.async.cg.shared.global [%0], [%1], 16;"
                     :: "r"(aB + sw), "l"(srcA));
        asm volatile("cp.async.cg.shared.global [%0], [%1], 16;"
                     :: "r"(bB + sw), "l"(srcB));
    }
    asm volatile("cp.async.commit_group;" ::: "memory");
}

// ---------------- the one persistent kernel ----------------
__global__ void __launch_bounds__(NT, 2) mmd_all_kernel(
        const float* __restrict__ xs, const float* __restrict__ xt,
        float* __restrict__ out) {
    extern __shared__ char smem[];
    uint32_t sb = smem_u32(smem);
    int tid = threadIdx.x, wid = tid >> 5, lane = tid & 31;
    int bid = blockIdx.x, grid = gridDim.x;

    // ======== phase 1: convert to fp16, row norms, column partials ========
    // scol2[warp][256] in the (currently idle) stage area: exclusive writes.
    float* scol2 = (float*)smem;                 // 8 * 256 floats = 8 KB
    float* ssum  = (float*)(smem + SQ_OFF);      // 8 floats
    int c0 = lane * 8;
    #pragma unroll
    for (int j = 0; j < 8; j++) scol2[wid * DD + c0 + j] = 0.f;
    float warp_sumsq = 0.f;                      // valid on lane 0

    for (int g = bid; g < NTOT / 8; g += grid) {
        int row = g * 8 + wid;
        const float* p = (row < BHALF) ? xs + (size_t)row * DD
                                       : xt + (size_t)(row - BHALF) * DD;
        float4 v0 = *(const float4*)(p + c0);
        float4 v1 = *(const float4*)(p + c0 + 4);
        float f[8] = {v0.x, v0.y, v0.z, v0.w, v1.x, v1.y, v1.z, v1.w};
        float s = 0.f;
        half2* q2 = (half2*)(g_x + (size_t)row * DD + c0);
        #pragma unroll
        for (int j = 0; j < 4; j++) {
            __half h0 = __float2half_rn(f[2 * j]);
            __half h1 = __float2half_rn(f[2 * j + 1]);
            q2[j] = __halves2half2(h0, h1);
            float t0 = __half2float(h0), t1 = __half2float(h1);
            s = fmaf(t0, t0, s); s = fmaf(t1, t1, s);
            scol2[wid * DD + c0 + 2 * j]     += t0;
            scol2[wid * DD + c0 + 2 * j + 1] += t1;
        }
        #pragma unroll
        for (int o = 16; o; o >>= 1) s += __shfl_xor_sync(0xffffffffu, s, o);
        if (lane == 0) { g_sq[row] = s; warp_sumsq += s; }
    }
    if (lane == 0) ssum[wid] = warp_sumsq;
    __syncthreads();
    // column partials -> global (one float atomic per thread)
    {
        float cp = 0.f;
        #pragma unroll
        for (int w = 0; w < 8; w++) cp += scol2[w * DD + tid];
        atomicAdd(&g_colsum[tid], cp);
    }
    if (tid == 0) {
        float b = 0.f;
        #pragma unroll
        for (int w = 0; w < 8; w++) b += ssum[w];
        atomicAdd(&g_sumsq, (double)b);
        if (bid == 0) g_acc = 0.0;   // no CTA touches g_acc until after barrier
    }

    // ======== device-wide barrier (all CTAs co-resident: grid = 2*SMs) ========
    __threadfence();
    __syncthreads();
    if (tid == 0) {
        atomicAdd(&g_bar, 1u);
        while (*(volatile unsigned*)&g_bar < (unsigned)grid) __nanosleep(64);
    }
    __syncthreads();
    __threadfence();

    // ======== phase 2: bandwidth (computed identically in every CTA) ========
    {
        double* sh = (double*)smem;              // stage area still free
        float cs = g_colsum[tid];
        sh[tid] = (double)cs * (double)cs;
        __syncthreads();
        for (int s2 = 128; s2; s2 >>= 1) {
            if (tid < s2) sh[tid] += sh[tid + s2];
            __syncthreads();
        }
        if (tid == 0) {
            double n = (double)NTOT;
            double sumL2 = 2.0 * n * g_sumsq - 2.0 * sh[0];
            double bw = sumL2 / (n * n - n) / 4.0;
            *(float*)(smem + MS_OFF) = (float)(1.4426950408889634 / (bw * 16.0));
        }
        __syncthreads();
    }
    float m = *(float*)(smem + MS_OFF);

    // ======== phase 3: persistent tile loop with cross-tile pipeline ========
    int grp = lane >> 3, rin = lane & 7;
    int wm = (wid >> 2) * 64;
    int wn = (wid & 3) * 32;
    int aRow = wm + (grp & 1) * 8 + rin;
    int aKB  = (grp >> 1) * 16;
    int bRow = wn + (grp >> 1) * 8 + rin;
    int bKB  = (grp & 1) * 16;
    uint32_t aMask = (uint32_t)((aRow & 7) << 4);
    uint32_t bMask = (uint32_t)((bRow & 7) << 4);

    float* sqrow = (float*)(smem + SQ_OFF);
    float* sqcol = sqrow + TILE;
    float* red   = (float*)(smem + RED_OFF);

    int t0 = bid;
    if (t0 < NBLK) {
        int ti, tj;
        tile_decode(t0, ti, tj);
        load_chunk(sb, 0, g_x + (size_t)ti * TILE * DD,
                          g_x + (size_t)tj * TILE * DD, 0, tid);
    }

    for (int t = t0; t < NBLK; t += grid) {
        int ti, tj;
        tile_decode(t, ti, tj);
        const __half* gA = g_x + (size_t)ti * TILE * DD;
        const __half* gB = g_x + (size_t)tj * TILE * DD;

        __syncthreads();   // prev epilogue done with sq/red smem
        if (tid < TILE) sqrow[tid] = g_sq[ti * TILE + tid];
        else            sqcol[tid - TILE] = g_sq[tj * TILE + (tid - TILE)];

        uint32_t acc[4][4][2];
        #pragma unroll
        for (int a = 0; a < 4; a++)
            #pragma unroll
            for (int c = 0; c < 4; c++) { acc[a][c][0] = 0u; acc[a][c][1] = 0u; }

        #pragma unroll
        for (int ck = 0; ck < NCHUNK; ck++) {
            bool issued = true;
            if (ck < NCHUNK - 1) {
                load_chunk(sb, (ck + 1) & 1, gA, gB, (ck + 1) * KC, tid);
            } else {
                int tn = t + grid;
                if (tn < NBLK) {       // prefetch next tile's chunk 0
                    int tin, tjn;
                    tile_decode(tn, tin, tjn);
                    load_chunk(sb, 0, g_x + (size_t)tin * TILE * DD,
                                      g_x + (size_t)tjn * TILE * DD, 0, tid);
                } else issued = false;
            }
            if (issued) asm volatile("cp.async.wait_group 1;" ::: "memory");
            else        asm volatile("cp.async.wait_group 0;" ::: "memory");
            __syncthreads();

            uint32_t aB = sb + (uint32_t)(ck & 1) * STAGE_BYTES;
            uint32_t bB = aB + B_OFF;
            #pragma unroll
            for (int ks = 0; ks < 4; ks++) {
                uint32_t a[4][4], bf[2][4];
                #pragma unroll
                for (int mt = 0; mt < 4; mt++) {
                    uint32_t addr = aB + (uint32_t)((aRow + mt * 16) * 128)
                                  + (((uint32_t)(ks * 32 + aKB)) ^ aMask);
                    ldsm_x4(a[mt][0], a[mt][1], a[mt][2], a[mt][3], addr);
                }
                #pragma unroll
                for (int nh = 0; nh < 2; nh++) {
                    uint32_t addr = bB + (uint32_t)((bRow + nh * 16) * 128)
                                  + (((uint32_t)(ks * 32 + bKB)) ^ bMask);
                    ldsm_x4(bf[nh][0], bf[nh][1], bf[nh][2], bf[nh][3], addr);
                }
                #pragma unroll
                for (int mt = 0; mt < 4; mt++)
                    #pragma unroll
                    for (int nt = 0; nt < 4; nt++)
                        mma_f16acc(acc[mt][nt], a[mt],
                                   bf[nt >> 1][(nt & 1) * 2],
                                   bf[nt >> 1][(nt & 1) * 2 + 1]);
            }
            __syncthreads();
        }

        // ---- epilogue (overlaps next tile's chunk-0 load) ----
        int rbase = wm + (lane >> 2);
        int cbase = wn + ((lane & 3) << 1);
        int rglob = ti * TILE, cglob = tj * TILE;
        float total = 0.f;
        #pragma unroll
        for (int mt = 0; mt < 4; mt++) {
            int rr = rbase + mt * 16;
            #pragma unroll
            for (int nt = 0; nt < 4; nt++) {
                int cc = cbase + nt * 8;
                float sb0 = sqcol[cc], sb1 = sqcol[cc + 1];
                #pragma unroll
                for (int e2 = 0; e2 < 2; e2++) {
                    int rl = rr + e2 * 8;
                    float sa = sqrow[rl];
                    float2 dv = __half22float2(*(const half2*)&acc[mt][nt][e2]);
                    float L2a = fmaxf(sa + sb0 - 2.f * dv.x, 0.f);
                    float L2b = fmaxf(sa + sb1 - 2.f * dv.y, 0.f);
                    float ea, eb;
                    asm("ex2.approx.ftz.f32 %0, %1;" : "=f"(ea) : "f"(-L2a * m));
                    asm("ex2.approx.ftz.f32 %0, %1;" : "=f"(eb) : "f"(-L2b * m));
                    float ea1 = ea * ea, ea2 = ea1 * ea1, ea3 = ea2 * ea2, ea4 = ea3 * ea3;
                    float eb1 = eb * eb, eb2 = eb1 * eb1, eb3 = eb2 * eb2, eb4 = eb3 * eb3;
                    float kva = ((ea + ea1) + (ea2 + ea3)) + ea4;
                    float kvb = ((eb + eb1) + (eb2 + eb3)) + eb4;
                    int rg = rglob + rl, cg = cglob + cc;
                    total += (rg > cg)     ? kva : 0.f;
                    total += (rg > cg + 1) ? kvb : 0.f;
                }
            }
        }
        total *= (((ti < 32) == (tj < 32)) ? 2.f : -2.f);

        #pragma unroll
        for (int o = 16; o; o >>= 1) total += __shfl_xor_sync(0xffffffffu, total, o);
        if (lane == 0) red[wid] = total;
        __syncthreads();
        if (tid == 0) {
            float s = 0.f;
            #pragma unroll
            for (int w = 0; w < 8; w++) s += red[w];
            atomicAdd(&g_acc, (double)s);
        }
    }

    // ======== finalize: last CTA writes output + resets all state ========
    __shared__ int s_flag;
    __threadfence();
    __syncthreads();
    if (tid == 0)
        s_flag = (atomicAdd(&g_done, 1u) == (unsigned)grid - 1u);
    __syncthreads();
    if (s_flag) {
        g_colsum[tid] = 0.f;
        if (tid == 0) {
            out[0] = (float)((g_acc + (double)NTOT * 5.0) /
                             ((double)BHALF * (double)BHALF));
            g_sumsq = 0.0;
            g_bar = 0u;
            g_done = 0u;
        }
    }
}

// ---------------- launch ----------------
extern "C" void kernel_launch(void* const* d_in, const int* in_sizes, int n_in,
                              void* d_out, int out_size) {
    const float* xs = (const float*)d_in[0];
    const float* xt = (const float*)d_in[1];
    float* out = (float*)d_out;

    static int grid = 0;
    if (grid == 0) {
        int sms = 148;
        cudaDeviceGetAttribute(&sms, cudaDevAttrMultiProcessorCount, 0);
        cudaFuncSetAttribute(mmd_all_kernel,
                             cudaFuncAttributeMaxDynamicSharedMemorySize, SMEM_TOTAL);
        grid = sms * 2;
    }
    mmd_all_kernel<<<grid, NT, SMEM_TOTAL>>>(xs, xt, out);
}